// round 11
// baseline (speedup 1.0000x reference)
#include <cuda_runtime.h>
#include <cstdint>

#define B      16
#define T      4096
#define D      256
#define TOPK   7
#define NBLK   (B * D / 4)          // 1024 blocks, 2 complex series (4 channels) each

// padded smem index: +1 float2 every 16
#define SPAD(i) ((i) + ((i) >> 4))
#define SER_PAD 4356

// slot where Y[alpha] lands after dft16
#define SL(al) ((((al) & 3) << 2) | ((al) >> 2))

// per-series params: float4(k_as_int_bits, C=Re/1024, S=Im/1024, twoC=2cos(2pik/T))
__device__ float4 g_params[B * D * TOPK];

__device__ __forceinline__ float2 cmul(float2 a, float2 b) {
    return make_float2(a.x * b.x - a.y * b.y, a.x * b.y + a.y * b.x);
}
__device__ __forceinline__ float2 cmulf(float2 a, float br, float bi) {
    return make_float2(a.x * br - a.y * bi, a.x * bi + a.y * br);
}

__device__ __forceinline__ void bf4(float2& a0, float2& a1, float2& a2, float2& a3) {
    float2 t0 = make_float2(a0.x + a2.x, a0.y + a2.y);
    float2 t1 = make_float2(a0.x - a2.x, a0.y - a2.y);
    float2 t2 = make_float2(a1.x + a3.x, a1.y + a3.y);
    float2 t3 = make_float2(a1.x - a3.x, a1.y - a3.y);
    a0 = make_float2(t0.x + t2.x, t0.y + t2.y);
    a1 = make_float2(t1.x + t3.y, t1.y - t3.x);   // t1 - i*t3
    a2 = make_float2(t0.x - t2.x, t0.y - t2.y);
    a3 = make_float2(t1.x - t3.y, t1.y + t3.x);   // t1 + i*t3
}

// 16-point forward DFT, natural-order input; Y[alpha] ends in slot SL(alpha).
__device__ __forceinline__ void dft16(float2* r) {
    const float C1 = 0.9238795325112867f;
    const float S1 = 0.3826834323650898f;
    const float A  = 0.7071067811865476f;
    bf4(r[0], r[4], r[8],  r[12]);
    bf4(r[1], r[5], r[9],  r[13]);
    r[5]  = cmulf(r[5],  C1, -S1);
    r[9]  = cmulf(r[9],  A,  -A);
    r[13] = cmulf(r[13], S1, -C1);
    bf4(r[2], r[6], r[10], r[14]);
    r[6]  = cmulf(r[6],  A,  -A);
    r[10] = make_float2(r[10].y, -r[10].x);
    r[14] = cmulf(r[14], -A, -A);
    bf4(r[3], r[7], r[11], r[15]);
    r[7]  = cmulf(r[7],  S1, -C1);
    r[11] = cmulf(r[11], -A, -A);
    r[15] = cmulf(r[15], -C1, S1);
    bf4(r[0],  r[1],  r[2],  r[3]);
    bf4(r[4],  r[5],  r[6],  r[7]);
    bf4(r[8],  r[9],  r[10], r[11]);
    bf4(r[12], r[13], r[14], r[15]);
}

#define APP(al, w) r[SL(al)] = cmul(r[SL(al)], w)

// apply w1^al to slot SL(al), al=1..15 (4 rolling chains)
__device__ __forceinline__ void twid_apply15(float2* r, float2 w1) {
    float2 w2 = cmul(w1, w1);
    float2 w3 = cmul(w2, w1);
    float2 w4 = cmul(w2, w2);
    float2 wa = w1, wb = w2, wc = w3, wd = w4;
    APP(1, wa); APP(2, wb); APP(3, wc); APP(4, wd);
    const float2 s = w4;
    wa = cmul(wa, s); wb = cmul(wb, s); wc = cmul(wc, s); wd = cmul(wd, s);
    APP(5, wa); APP(6, wb); APP(7, wc); APP(8, wd);
    wa = cmul(wa, s); wb = cmul(wb, s); wc = cmul(wc, s); wd = cmul(wd, s);
    APP(9, wa); APP(10, wb); APP(11, wc); APP(12, wd);
    wa = cmul(wa, s); wb = cmul(wb, s); wc = cmul(wc, s);
    APP(13, wa); APP(14, wb); APP(15, wc);
}

// apply w0*s1^be to slot SL(be), be=0..15
__device__ __forceinline__ void twid_apply16(float2* r, float2 w0, float2 s1) {
    float2 s2 = cmul(s1, s1);
    float2 s3 = cmul(s2, s1);
    float2 s4 = cmul(s2, s2);
    float2 wa = w0, wb = cmul(w0, s1), wc = cmul(w0, s2), wd = cmul(w0, s3);
    APP(0, wa); APP(1, wb); APP(2, wc); APP(3, wd);
    wa = cmul(wa, s4); wb = cmul(wb, s4); wc = cmul(wc, s4); wd = cmul(wd, s4);
    APP(4, wa); APP(5, wb); APP(6, wc); APP(7, wd);
    wa = cmul(wa, s4); wb = cmul(wb, s4); wc = cmul(wc, s4); wd = cmul(wd, s4);
    APP(8, wa); APP(9, wb); APP(10, wc); APP(11, wd);
    wa = cmul(wa, s4); wb = cmul(wb, s4); wc = cmul(wc, s4); wd = cmul(wd, s4);
    APP(12, wa); APP(13, wb); APP(14, wc); APP(15, wd);
}

// ---------------------------------------------------------------------------
// Kernel 1: 512 threads, 2 packed complex series per block.
// Pass 1 loads global directly into registers (no smem staging round trip).
// Pass 3 keeps its outputs in registers for the magnitude phase (mirror-only LDS).
// ---------------------------------------------------------------------------
__global__ __launch_bounds__(512, 2)
void fft_topk_kernel(const float* __restrict__ x) {
    extern __shared__ float2 sm[];
    float2* zz   = sm;                       // 2 * SER_PAD
    float2* cand = sm + 2 * SER_PAD;         // [4 channels][8 warps * 7]

    const int tid = threadIdx.x;
    const int blk = blockIdx.x;
    const int b   = blk >> 6;
    const int d0  = (blk & 63) * 4;

    const int sid  = tid >> 8;
    const int tl   = tid & 255;
    const int lane = tid & 31;
    float2* Z = zz + sid * SER_PAD;
    float2 r[16];

    // ---------------- pass 1: direct global load (t = a*256 + tl) ----------
    {
        const float* px = x + ((size_t)(b * T + tl)) * D + d0;
        #pragma unroll
        for (int a = 0; a < 16; a++) {
            float4 v = *reinterpret_cast<const float4*>(px + (size_t)a * 256 * D);
            r[a] = sid ? make_float2(v.z, v.w) : make_float2(v.x, v.y);
        }
    }
    dft16(r);
    {
        float s, c; sincospif((float)(tl >> 4) * (1.0f / 128.0f), &s, &c);
        twid_apply15(r, make_float2(c, -s));
    }
    #pragma unroll
    for (int al = 0; al < 16; al++)
        Z[SPAD(al * 256 + tl)] = r[SL(al)];
    __syncthreads();

    // ---------------- pass 2: stride 16 ----------------
    const int alpha = tl >> 4, cc = tl & 15;
    {
        #pragma unroll
        for (int bb = 0; bb < 16; bb++)
            r[bb] = Z[SPAD(alpha * 256 + bb * 16 + cc)];
        dft16(r);
        float s0, c0, s1, c1;
        sincospif((float)(cc * alpha) * (1.0f / 2048.0f), &s0, &c0);
        sincospif((float)cc * (1.0f / 128.0f), &s1, &c1);
        twid_apply16(r, make_float2(c0, -s0), make_float2(c1, -s1));
        #pragma unroll
        for (int be = 0; be < 16; be++)
            Z[SPAD(alpha * 256 + be * 16 + cc)] = r[SL(be)];
    }
    __syncwarp();    // pass2->pass3 exchange is within a 16-thread group

    // ---------------- pass 3: stride 1, scatter; keep r[] for magnitudes ---
    const int beta = tl & 15;
    const int kbase = beta * 16 + alpha;     // low 8 bits of this thread's bins
    {
        #pragma unroll
        for (int c2 = 0; c2 < 16; c2++)
            r[c2] = Z[SPAD(alpha * 256 + beta * 16 + c2)];
        __syncthreads();                 // all reads done before scatter writes
        dft16(r);
        #pragma unroll
        for (int ga = 0; ga < 16; ga++)
            Z[SPAD(ga * 256 + beta * 16 + alpha)] = r[SL(ga)];
    }
    __syncthreads();

    // ---------------- magnitudes: Zk from registers, only mirror from smem --
    float magA[8], magB[8];
    #pragma unroll
    for (int m = 0; m < 8; m++) {
        int k = m * 256 + kbase;             // bin this thread owns (k < 2048)
        const bool valid = (k != 0);
        int kk = valid ? k : 1;
        float2 Zk = r[SL(m)];                // own value (k = m*256+kbase)
        float2 Zn = Z[SPAD(4096 - kk)];      // mirror
        if (!valid) Zk = Z[SPAD(1)];         // dummy consistent pair
        float reA = 0.5f * (Zk.x + Zn.x), imA = 0.5f * (Zk.y - Zn.y);
        float reB = 0.5f * (Zk.y + Zn.y), imB = 0.5f * (Zn.x - Zk.x);
        magA[m] = valid ? (reA * reA + imA * imA) : -1.0f;
        magB[m] = valid ? (reB * reB + imB * imB) : -1.0f;
    }

    // ---------------- phase 1: warp-local top-7 (no block syncs) -----------
    const int wloc = (tid >> 5) & 7;     // warp within series
    #pragma unroll
    for (int r7 = 0; r7 < TOPK; r7++) {
        float bm = magA[0]; int bmi = 0;
        #pragma unroll
        for (int m = 1; m < 8; m++)
            if (magA[m] > bm) { bm = magA[m]; bmi = m; }
        int bk = bmi * 256 + kbase;
        #pragma unroll
        for (int o = 16; o > 0; o >>= 1) {
            float om = __shfl_down_sync(0xFFFFFFFFu, bm, o);
            int   ok = __shfl_down_sync(0xFFFFFFFFu, bk, o);
            if (om > bm) { bm = om; bk = ok; }
        }
        bm = __shfl_sync(0xFFFFFFFFu, bm, 0);
        bk = __shfl_sync(0xFFFFFFFFu, bk, 0);
        if ((bk & 255) == kbase) magA[bk >> 8] = -1.0f;
        if (lane == r7)
            cand[(sid * 2 + 0) * 56 + wloc * TOPK + r7] =
                make_float2(bm, __int_as_float(bk));

        bm = magB[0]; bmi = 0;
        #pragma unroll
        for (int m = 1; m < 8; m++)
            if (magB[m] > bm) { bm = magB[m]; bmi = m; }
        bk = bmi * 256 + kbase;
        #pragma unroll
        for (int o = 16; o > 0; o >>= 1) {
            float om = __shfl_down_sync(0xFFFFFFFFu, bm, o);
            int   ok = __shfl_down_sync(0xFFFFFFFFu, bk, o);
            if (om > bm) { bm = om; bk = ok; }
        }
        bm = __shfl_sync(0xFFFFFFFFu, bm, 0);
        bk = __shfl_sync(0xFFFFFFFFu, bk, 0);
        if ((bk & 255) == kbase) magB[bk >> 8] = -1.0f;
        if (lane == r7)
            cand[(sid * 2 + 1) * 56 + wloc * TOPK + r7] =
                make_float2(bm, __int_as_float(bk));
    }
    __syncthreads();

    // ---------------- phase 2: merge 56 candidates per channel -------------
    const int wrp = tid >> 5;
    if (wrp < 4) {                       // warp q handles channel q = 2*ser+ch
        const float2* cs = cand + wrp * 56;
        float m0 = -3.0f, m1 = -3.0f; int k0 = 1, k1 = 1;
        if (lane < 28) {
            float2 e0 = cs[lane];      m0 = e0.x; k0 = __float_as_int(e0.y);
            float2 e1 = cs[lane + 28]; m1 = e1.x; k1 = __float_as_int(e1.y);
        }
        int savedK = 1;
        #pragma unroll
        for (int r7 = 0; r7 < TOPK; r7++) {
            float bm = m0; int bk = k0;
            if (m1 > bm) { bm = m1; bk = k1; }
            #pragma unroll
            for (int o = 16; o > 0; o >>= 1) {
                float om = __shfl_down_sync(0xFFFFFFFFu, bm, o);
                int   ok = __shfl_down_sync(0xFFFFFFFFu, bk, o);
                if (om > bm) { bm = om; bk = ok; }
            }
            bk = __shfl_sync(0xFFFFFFFFu, bk, 0);
            if (k0 == bk) m0 = -3.0f;
            if (k1 == bk) m1 = -3.0f;
            if (lane == r7) savedK = bk;
        }
        if (lane < TOPK) {
            const int ser = wrp >> 1, ch = wrp & 1;
            int k = savedK;
            float2* Zs = zz + ser * SER_PAD;
            float2 Zk = Zs[SPAD(k)];
            float2 Zn = Zs[SPAD(4096 - k)];
            float re, im;
            if (!ch) { re = 0.5f * (Zk.x + Zn.x); im = 0.5f * (Zk.y - Zn.y); }
            else     { re = 0.5f * (Zk.y + Zn.y); im = 0.5f * (Zn.x - Zk.x); }
            float twoC = 2.0f * cospif((float)k * (1.0f / 2048.0f));
            g_params[(size_t)(b * D + d0 + 2 * ser + ch) * TOPK + lane] =
                make_float4(__int_as_float(k), re * (1.0f / 1024.0f),
                            im * (1.0f / 1024.0f), twoC);
        }
    }
}

// ---------------------------------------------------------------------------
// Kernel 2: Chebyshev reconstruction, 128-sample chunks.
// Seeds: one sincospif for g(t0); g(t0-1) by backward rotation with
// (cosd, sind) = (twoC/2, sinpif(k/2048)).
// ---------------------------------------------------------------------------
__global__ __launch_bounds__(256)
void reconstruct_kernel(float* __restrict__ out) {
    const int d  = threadIdx.x;
    const int b  = blockIdx.y;
    const int t0 = blockIdx.x * 128;
    const size_t series = (size_t)b * D + d;

    float twoC[TOPK], g[TOPK], gp[TOPK];
    #pragma unroll
    for (int j = 0; j < TOPK; j++) {
        float4 p = g_params[series * TOPK + j];
        int k = __float_as_int(p.x);
        float C = p.y, S = p.z;
        twoC[j] = p.w;
        float cosd = 0.5f * p.w;
        float sind = sinpif((float)k * (1.0f / 2048.0f));   // k in (0,2048): sind>0
        int m1 = (k * t0) & (T - 1);
        float s1, c1;
        sincospif((float)m1 * (1.0f / 2048.0f), &s1, &c1);
        g[j] = C * c1 - S * s1;
        float cp = c1 * cosd + s1 * sind;     // cos(theta0 - d)
        float sp = s1 * cosd - c1 * sind;     // sin(theta0 - d)
        gp[j] = C * cp - S * sp;
    }

    float* orow = out + ((size_t)(b * T + t0)) * D + d;
    #pragma unroll 4
    for (int tt = 0; tt < 128; tt += 2) {
        float a0 = 0.0f;
        #pragma unroll
        for (int j = 0; j < TOPK; j++) a0 += g[j];
        orow[(size_t)tt * D] = a0;
        #pragma unroll
        for (int j = 0; j < TOPK; j++)
            gp[j] = fmaf(twoC[j], g[j], -gp[j]);
        float a1 = 0.0f;
        #pragma unroll
        for (int j = 0; j < TOPK; j++) a1 += gp[j];
        orow[(size_t)(tt + 1) * D] = a1;
        #pragma unroll
        for (int j = 0; j < TOPK; j++)
            g[j] = fmaf(twoC[j], gp[j], -g[j]);
    }
}

// ---------------------------------------------------------------------------
extern "C" void kernel_launch(void* const* d_in, const int* in_sizes, int n_in,
                              void* d_out, int out_size) {
    const float* x = (const float*)d_in[0];
    float* out = (float*)d_out;

    const size_t smem_bytes = (2 * SER_PAD + 224) * sizeof(float2);
    cudaFuncSetAttribute(fft_topk_kernel,
                         cudaFuncAttributeMaxDynamicSharedMemorySize,
                         (int)smem_bytes);

    fft_topk_kernel<<<NBLK, 512, smem_bytes>>>(x);
    reconstruct_kernel<<<dim3(T / 128, B), 256>>>(out);
}

// round 13
// speedup vs baseline: 1.1409x; 1.1409x over previous
#include <cuda_runtime.h>
#include <cstdint>

#define B      16
#define T      4096
#define D      256
#define TOPK   7
#define NBLK   (B * D / 4)          // 1024 blocks, 2 complex series (4 channels) each

// padded smem index: +1 float2 every 16.  All hot-loop indices are factored so
// the runtime part is computed ONCE and per-element offsets are immediates:
//   SPAD(a*256+tl)        = a*272 + SPAD(tl)
//   SPAD(al*256+b*16+c)   = al*272 + b*17 + c          (c < 16)
//   SPAD(4096-(m*256+tl)) = (15-m)*272 + SPAD(256-tl)
#define SPAD(i) ((i) + ((i) >> 4))
#define SER_PAD 4360

// slot where Y[alpha] lands after dft16
#define SL(al) ((((al) & 3) << 2) | ((al) >> 2))

// per-series params: float4(k_as_int_bits, C=Re/1024, S=Im/1024, twoC=2cos(2pik/T))
__device__ float4 g_params[B * D * TOPK];

__device__ __forceinline__ float2 cmul(float2 a, float2 b) {
    return make_float2(a.x * b.x - a.y * b.y, a.x * b.y + a.y * b.x);
}
__device__ __forceinline__ float2 cmulf(float2 a, float br, float bi) {
    return make_float2(a.x * br - a.y * bi, a.x * bi + a.y * br);
}

__device__ __forceinline__ void bf4(float2& a0, float2& a1, float2& a2, float2& a3) {
    float2 t0 = make_float2(a0.x + a2.x, a0.y + a2.y);
    float2 t1 = make_float2(a0.x - a2.x, a0.y - a2.y);
    float2 t2 = make_float2(a1.x + a3.x, a1.y + a3.y);
    float2 t3 = make_float2(a1.x - a3.x, a1.y - a3.y);
    a0 = make_float2(t0.x + t2.x, t0.y + t2.y);
    a1 = make_float2(t1.x + t3.y, t1.y - t3.x);   // t1 - i*t3
    a2 = make_float2(t0.x - t2.x, t0.y - t2.y);
    a3 = make_float2(t1.x - t3.y, t1.y + t3.x);   // t1 + i*t3
}

// 16-point forward DFT, natural-order input; Y[alpha] ends in slot SL(alpha).
__device__ __forceinline__ void dft16(float2* r) {
    const float C1 = 0.9238795325112867f;
    const float S1 = 0.3826834323650898f;
    const float A  = 0.7071067811865476f;
    bf4(r[0], r[4], r[8],  r[12]);
    bf4(r[1], r[5], r[9],  r[13]);
    r[5]  = cmulf(r[5],  C1, -S1);
    r[9]  = cmulf(r[9],  A,  -A);
    r[13] = cmulf(r[13], S1, -C1);
    bf4(r[2], r[6], r[10], r[14]);
    r[6]  = cmulf(r[6],  A,  -A);
    r[10] = make_float2(r[10].y, -r[10].x);
    r[14] = cmulf(r[14], -A, -A);
    bf4(r[3], r[7], r[11], r[15]);
    r[7]  = cmulf(r[7],  S1, -C1);
    r[11] = cmulf(r[11], -A, -A);
    r[15] = cmulf(r[15], -C1, S1);
    bf4(r[0],  r[1],  r[2],  r[3]);
    bf4(r[4],  r[5],  r[6],  r[7]);
    bf4(r[8],  r[9],  r[10], r[11]);
    bf4(r[12], r[13], r[14], r[15]);
}

#define APP(al, w) r[SL(al)] = cmul(r[SL(al)], w)

// apply w1^al to slot SL(al), al=1..15 (4 rolling chains)
__device__ __forceinline__ void twid_apply15(float2* r, float2 w1) {
    float2 w2 = cmul(w1, w1);
    float2 w3 = cmul(w2, w1);
    float2 w4 = cmul(w2, w2);
    float2 wa = w1, wb = w2, wc = w3, wd = w4;
    APP(1, wa); APP(2, wb); APP(3, wc); APP(4, wd);
    const float2 s = w4;
    wa = cmul(wa, s); wb = cmul(wb, s); wc = cmul(wc, s); wd = cmul(wd, s);
    APP(5, wa); APP(6, wb); APP(7, wc); APP(8, wd);
    wa = cmul(wa, s); wb = cmul(wb, s); wc = cmul(wc, s); wd = cmul(wd, s);
    APP(9, wa); APP(10, wb); APP(11, wc); APP(12, wd);
    wa = cmul(wa, s); wb = cmul(wb, s); wc = cmul(wc, s);
    APP(13, wa); APP(14, wb); APP(15, wc);
}

// apply w0*s1^be to slot SL(be), be=0..15
__device__ __forceinline__ void twid_apply16(float2* r, float2 w0, float2 s1) {
    float2 s2 = cmul(s1, s1);
    float2 s3 = cmul(s2, s1);
    float2 s4 = cmul(s2, s2);
    float2 wa = w0, wb = cmul(w0, s1), wc = cmul(w0, s2), wd = cmul(w0, s3);
    APP(0, wa); APP(1, wb); APP(2, wc); APP(3, wd);
    wa = cmul(wa, s4); wb = cmul(wb, s4); wc = cmul(wc, s4); wd = cmul(wd, s4);
    APP(4, wa); APP(5, wb); APP(6, wc); APP(7, wd);
    wa = cmul(wa, s4); wb = cmul(wb, s4); wc = cmul(wc, s4); wd = cmul(wd, s4);
    APP(8, wa); APP(9, wb); APP(10, wc); APP(11, wd);
    wa = cmul(wa, s4); wb = cmul(wb, s4); wc = cmul(wc, s4); wd = cmul(wd, s4);
    APP(12, wa); APP(13, wb); APP(14, wc); APP(15, wd);
}

// ---------------------------------------------------------------------------
// Kernel 1: 512 threads, 2 packed complex series per block (proven shape),
// all smem addressing via hoisted bases + immediate offsets.
// ---------------------------------------------------------------------------
__global__ __launch_bounds__(512, 2)
void fft_topk_kernel(const float* __restrict__ x) {
    extern __shared__ float2 sm[];
    float2* zz   = sm;                       // 2 * SER_PAD
    float2* cand = sm + 2 * SER_PAD;         // [4 channels][8 warps * 7]

    const int tid = threadIdx.x;
    const int blk = blockIdx.x;
    const int b   = blk >> 6;
    const int d0  = (blk & 63) * 4;

    // staged load: each thread loads one float4 (4 channels), writes 2 series
    #pragma unroll
    for (int it = 0; it < 8; it++) {
        int t = tid + it * 512;
        float4 v = *reinterpret_cast<const float4*>(
            x + ((size_t)(b * T + t)) * D + d0);
        int sp = SPAD(t);
        zz[sp]           = make_float2(v.x, v.y);
        zz[SER_PAD + sp] = make_float2(v.z, v.w);
    }
    __syncthreads();

    const int sid  = tid >> 8;
    const int tl   = tid & 255;
    const int lane = tid & 31;
    float2* Z = zz + sid * SER_PAD;
    float2 r[16];

    // ---------------- pass 1: stride 256; base = SPAD(tl) ------------------
    {
        float2* zt = Z + SPAD(tl);
        #pragma unroll
        for (int a = 0; a < 16; a++) r[a] = zt[a * 272];
        dft16(r);
        float s, c; sincospif((float)(tl >> 4) * (1.0f / 128.0f), &s, &c);
        twid_apply15(r, make_float2(c, -s));
        #pragma unroll
        for (int al = 0; al < 16; al++) zt[al * 272] = r[SL(al)];
    }
    __syncthreads();

    // ---------------- pass 2: stride 16; base = alpha*272 + cc -------------
    const int alpha = tl >> 4, cc = tl & 15;
    {
        float2* zt = Z + alpha * 272 + cc;
        #pragma unroll
        for (int bb = 0; bb < 16; bb++) r[bb] = zt[bb * 17];
        dft16(r);
        float s0, c0, s1, c1;
        sincospif((float)(cc * alpha) * (1.0f / 2048.0f), &s0, &c0);
        sincospif((float)cc * (1.0f / 128.0f), &s1, &c1);
        twid_apply16(r, make_float2(c0, -s0), make_float2(c1, -s1));
        #pragma unroll
        for (int be = 0; be < 16; be++) zt[be * 17] = r[SL(be)];
    }
    __syncwarp();    // pass2->pass3 exchange stays within a 16-thread group

    // ---------------- pass 3: contiguous read, strided scatter -------------
    const int beta = tl & 15;
    {
        float2* zr = Z + alpha * 272 + beta * 17;       // + c2 (immediate)
        #pragma unroll
        for (int c2 = 0; c2 < 16; c2++) r[c2] = zr[c2];
        __syncthreads();                 // all reads done before scatter writes
        dft16(r);
        float2* zw = Z + beta * 17 + alpha;             // + ga*272 (immediate)
        #pragma unroll
        for (int ga = 0; ga < 16; ga++) zw[ga * 272] = r[SL(ga)];
    }
    __syncthreads();

    // ---------------- magnitudes: bases SPAD(tl) and SPAD(256-tl) ----------
    float magA[8], magB[8];
    {
        const float2* zk = Z + SPAD(tl);                // bin m*256+tl at m*272
        const float2* zn = Z + SPAD(256 - tl);          // mirror at (15-m)*272
        #pragma unroll
        for (int m = 0; m < 8; m++) {
            const bool valid = (m * 256 + tl) != 0;
            float2 Zk = zk[m * 272];
            float2 Zn = zn[(15 - m) * 272];
            float reA = 0.5f * (Zk.x + Zn.x), imA = 0.5f * (Zk.y - Zn.y);
            float reB = 0.5f * (Zk.y + Zn.y), imB = 0.5f * (Zn.x - Zk.x);
            magA[m] = valid ? (reA * reA + imA * imA) : -1.0f;
            magB[m] = valid ? (reB * reB + imB * imB) : -1.0f;
        }
    }

    // ---------------- phase 1: warp-local top-7 (no block syncs) -----------
    const int wloc = (tid >> 5) & 7;     // warp within series
    #pragma unroll
    for (int r7 = 0; r7 < TOPK; r7++) {
        float bm = magA[0]; int bmi = 0;
        #pragma unroll
        for (int m = 1; m < 8; m++)
            if (magA[m] > bm) { bm = magA[m]; bmi = m; }
        int bk = bmi * 256 + tl;
        #pragma unroll
        for (int o = 16; o > 0; o >>= 1) {
            float om = __shfl_down_sync(0xFFFFFFFFu, bm, o);
            int   ok = __shfl_down_sync(0xFFFFFFFFu, bk, o);
            if (om > bm) { bm = om; bk = ok; }
        }
        bm = __shfl_sync(0xFFFFFFFFu, bm, 0);
        bk = __shfl_sync(0xFFFFFFFFu, bk, 0);
        if ((bk & 255) == tl) magA[bk >> 8] = -1.0f;
        if (lane == r7)
            cand[(sid * 2 + 0) * 56 + wloc * TOPK + r7] =
                make_float2(bm, __int_as_float(bk));

        bm = magB[0]; bmi = 0;
        #pragma unroll
        for (int m = 1; m < 8; m++)
            if (magB[m] > bm) { bm = magB[m]; bmi = m; }
        bk = bmi * 256 + tl;
        #pragma unroll
        for (int o = 16; o > 0; o >>= 1) {
            float om = __shfl_down_sync(0xFFFFFFFFu, bm, o);
            int   ok = __shfl_down_sync(0xFFFFFFFFu, bk, o);
            if (om > bm) { bm = om; bk = ok; }
        }
        bm = __shfl_sync(0xFFFFFFFFu, bm, 0);
        bk = __shfl_sync(0xFFFFFFFFu, bk, 0);
        if ((bk & 255) == tl) magB[bk >> 8] = -1.0f;
        if (lane == r7)
            cand[(sid * 2 + 1) * 56 + wloc * TOPK + r7] =
                make_float2(bm, __int_as_float(bk));
    }
    __syncthreads();

    // ---------------- phase 2: merge 56 candidates per channel -------------
    const int wrp = tid >> 5;
    if (wrp < 4) {                       // warp q handles channel q = 2*ser+ch
        const float2* cs = cand + wrp * 56;
        float m0 = -3.0f, m1 = -3.0f; int k0 = 1, k1 = 1;
        if (lane < 28) {
            float2 e0 = cs[lane];      m0 = e0.x; k0 = __float_as_int(e0.y);
            float2 e1 = cs[lane + 28]; m1 = e1.x; k1 = __float_as_int(e1.y);
        }
        int savedK = 1;
        #pragma unroll
        for (int r7 = 0; r7 < TOPK; r7++) {
            float bm = m0; int bk = k0;
            if (m1 > bm) { bm = m1; bk = k1; }
            #pragma unroll
            for (int o = 16; o > 0; o >>= 1) {
                float om = __shfl_down_sync(0xFFFFFFFFu, bm, o);
                int   ok = __shfl_down_sync(0xFFFFFFFFu, bk, o);
                if (om > bm) { bm = om; bk = ok; }
            }
            bk = __shfl_sync(0xFFFFFFFFu, bk, 0);
            if (k0 == bk) m0 = -3.0f;
            if (k1 == bk) m1 = -3.0f;
            if (lane == r7) savedK = bk;
        }
        if (lane < TOPK) {
            const int ser = wrp >> 1, ch = wrp & 1;
            int k = savedK;
            float2* Zs = zz + ser * SER_PAD;
            float2 Zk = Zs[SPAD(k)];
            float2 Zn = Zs[SPAD(4096 - k)];
            float re, im;
            if (!ch) { re = 0.5f * (Zk.x + Zn.x); im = 0.5f * (Zk.y - Zn.y); }
            else     { re = 0.5f * (Zk.y + Zn.y); im = 0.5f * (Zn.x - Zk.x); }
            float twoC = 2.0f * cospif((float)k * (1.0f / 2048.0f));
            g_params[(size_t)(b * D + d0 + 2 * ser + ch) * TOPK + lane] =
                make_float4(__int_as_float(k), re * (1.0f / 1024.0f),
                            im * (1.0f / 1024.0f), twoC);
        }
    }
}

// ---------------------------------------------------------------------------
// Kernel 2: Chebyshev reconstruction, 128-sample chunks.
// Seeds: one sincospif for g(t0); g(t0-1) by backward rotation with
// (cosd, sind) = (twoC/2, sinpif(k/2048)).
// ---------------------------------------------------------------------------
__global__ __launch_bounds__(256)
void reconstruct_kernel(float* __restrict__ out) {
    const int d  = threadIdx.x;
    const int b  = blockIdx.y;
    const int t0 = blockIdx.x * 128;
    const size_t series = (size_t)b * D + d;

    float twoC[TOPK], g[TOPK], gp[TOPK];
    #pragma unroll
    for (int j = 0; j < TOPK; j++) {
        float4 p = g_params[series * TOPK + j];
        int k = __float_as_int(p.x);
        float C = p.y, S = p.z;
        twoC[j] = p.w;
        float cosd = 0.5f * p.w;
        float sind = sinpif((float)k * (1.0f / 2048.0f));   // k in (0,2048): sind>0
        int m1 = (k * t0) & (T - 1);
        float s1, c1;
        sincospif((float)m1 * (1.0f / 2048.0f), &s1, &c1);
        g[j] = C * c1 - S * s1;
        float cp = c1 * cosd + s1 * sind;     // cos(theta0 - d)
        float sp = s1 * cosd - c1 * sind;     // sin(theta0 - d)
        gp[j] = C * cp - S * sp;
    }

    float* orow = out + ((size_t)(b * T + t0)) * D + d;
    #pragma unroll 4
    for (int tt = 0; tt < 128; tt += 2) {
        float a0 = 0.0f;
        #pragma unroll
        for (int j = 0; j < TOPK; j++) a0 += g[j];
        orow[(size_t)tt * D] = a0;
        #pragma unroll
        for (int j = 0; j < TOPK; j++)
            gp[j] = fmaf(twoC[j], g[j], -gp[j]);
        float a1 = 0.0f;
        #pragma unroll
        for (int j = 0; j < TOPK; j++) a1 += gp[j];
        orow[(size_t)(tt + 1) * D] = a1;
        #pragma unroll
        for (int j = 0; j < TOPK; j++)
            g[j] = fmaf(twoC[j], gp[j], -g[j]);
    }
}

// ---------------------------------------------------------------------------
extern "C" void kernel_launch(void* const* d_in, const int* in_sizes, int n_in,
                              void* d_out, int out_size) {
    const float* x = (const float*)d_in[0];
    float* out = (float*)d_out;

    const size_t smem_bytes = (2 * SER_PAD + 224) * sizeof(float2);
    cudaFuncSetAttribute(fft_topk_kernel,
                         cudaFuncAttributeMaxDynamicSharedMemorySize,
                         (int)smem_bytes);

    fft_topk_kernel<<<NBLK, 512, smem_bytes>>>(x);
    reconstruct_kernel<<<dim3(T / 128, B), 256>>>(out);
}